// round 1
// baseline (speedup 1.0000x reference)
#include <cuda_runtime.h>
#include <math.h>

#define NTHREADS 64
#define NBLOCKS  1024        // 65536 / 64
#define TSTEPS   128

static __device__ float g_partial[NBLOCKS];

__device__ __forceinline__ float sigmoidf_(float x) {
    // 1/(1+e^-x): EX2 + RCP. Saturates correctly at extremes.
    return __fdividef(1.0f, 1.0f + __expf(-x));
}
__device__ __forceinline__ float tanhf_(float x) {
    // 1 - 2/(e^{2x}+1): robust at +/-inf (e->inf => 1, e->0 => -1)
    return 1.0f - __fdividef(2.0f, __expf(2.0f * x) + 1.0f);
}

__global__ __launch_bounds__(NTHREADS)
void recdyn_kernel(const float* __restrict__ hist,   // (B,1,T,3)
                   const float* __restrict__ h0,     // (1,B,1)
                   const float* __restrict__ c0,     // (1,B,1)
                   const float* __restrict__ target, // (B,1,3)
                   const float* __restrict__ Wih,    // (4,3)
                   const float* __restrict__ Whh,    // (4,1)
                   const float* __restrict__ bih,    // (4)
                   const float* __restrict__ bhh,    // (4)
                   const float* __restrict__ Wm,     // (3,128)
                   const float* __restrict__ bm,     // (3)
                   const float* __restrict__ Wv,     // (6,128)
                   const float* __restrict__ bv)     // (6)
{
    // Weights transposed into smem: row t holds [Wm0,Wm1,Wm2, Wv0..Wv5, pad x3]
    __shared__ float sw[TSTEPS * 12];
    __shared__ float sred[NTHREADS];

    for (int i = threadIdx.x; i < TSTEPS * 12; i += NTHREADS) {
        int t = i / 12, j = i % 12;
        float v = 0.0f;
        if (j < 3)      v = Wm[j * TSTEPS + t];
        else if (j < 9) v = Wv[(j - 3) * TSTEPS + t];
        sw[i] = v;
    }
    __syncthreads();

    const int b = blockIdx.x * NTHREADS + threadIdx.x;
    const float* xb = hist + (size_t)b * (TSTEPS * 3);

    // ---- rotation matrix from last 3 timesteps ----
    float v1x = xb[127*3+0], v1y = xb[127*3+1], v1z = xb[127*3+2];
    float v2x = xb[126*3+0], v2y = xb[126*3+1], v2z = xb[126*3+2];
    float v3x = xb[125*3+0], v3y = xb[125*3+1], v3z = xb[125*3+2];

    float n1 = rsqrtf(v1x*v1x + v1y*v1y + v1z*v1z);
    float b1x = v1x*n1, b1y = v1y*n1, b1z = v1z*n1;

    float p  = v2x*b1x + v2y*b1y + v2z*b1z;
    float a2x = v2x - p*b1x, a2y = v2y - p*b1y, a2z = v2z - p*b1z;
    float n2 = rsqrtf(a2x*a2x + a2y*a2y + a2z*a2z);
    float b2x = a2x*n2, b2y = a2y*n2, b2z = a2z*n2;

    float b3x = b1y*b2z - b1z*b2y;
    float b3y = b1z*b2x - b1x*b2z;
    float b3z = b1x*b2y - b1y*b2x;

    float sgn = (v3x*b3x + v3y*b3y + v3z*b3z) > 0.0f ? 1.0f : -1.0f;
    float c3x = sgn*b3x, c3y = sgn*b3y, c3z = sgn*b3z;

    // ---- fold rotation into input weights: Wp[k][m] = sum_i Wih[k][i]*b_i[m] ----
    float wih[12];
    #pragma unroll
    for (int k = 0; k < 12; ++k) wih[k] = Wih[k];
    float wp[4][3];
    #pragma unroll
    for (int k = 0; k < 4; ++k) {
        wp[k][0] = wih[k*3+0]*b1x + wih[k*3+1]*b2x + wih[k*3+2]*c3x;
        wp[k][1] = wih[k*3+0]*b1y + wih[k*3+1]*b2y + wih[k*3+2]*c3y;
        wp[k][2] = wih[k*3+0]*b1z + wih[k*3+1]*b2z + wih[k*3+2]*c3z;
    }
    float wh0 = Whh[0], wh1 = Whh[1], wh2 = Whh[2], wh3 = Whh[3];
    float bb0 = bih[0] + bhh[0];
    float bb1 = bih[1] + bhh[1];
    float bb2 = bih[2] + bhh[2];
    float bb3 = bih[3] + bhh[3];

    // ---- LSTM scan + on-the-fly head accumulation ----
    float h = h0[b], c = c0[b];
    float am0 = 0.f, am1 = 0.f, am2 = 0.f;
    float av0 = 0.f, av1 = 0.f, av2 = 0.f, av3 = 0.f, av4 = 0.f, av5 = 0.f;

    const float4* x4 = reinterpret_cast<const float4*>(xb);

    for (int g = 0; g < 32; ++g) {
        float4 qa = x4[g*3+0];
        float4 qb = x4[g*3+1];
        float4 qc = x4[g*3+2];
        float xs[12] = {qa.x, qa.y, qa.z, qa.w,
                        qb.x, qb.y, qb.z, qb.w,
                        qc.x, qc.y, qc.z, qc.w};
        #pragma unroll
        for (int k = 0; k < 4; ++k) {
            const int t = g*4 + k;
            float x0 = xs[3*k+0], x1 = xs[3*k+1], x2 = xs[3*k+2];

            float gi = fmaf(x0, wp[0][0], fmaf(x1, wp[0][1], fmaf(x2, wp[0][2], fmaf(h, wh0, bb0))));
            float gf = fmaf(x0, wp[1][0], fmaf(x1, wp[1][1], fmaf(x2, wp[1][2], fmaf(h, wh1, bb1))));
            float gg = fmaf(x0, wp[2][0], fmaf(x1, wp[2][1], fmaf(x2, wp[2][2], fmaf(h, wh2, bb2))));
            float go = fmaf(x0, wp[3][0], fmaf(x1, wp[3][1], fmaf(x2, wp[3][2], fmaf(h, wh3, bb3))));

            float si = sigmoidf_(gi);
            float sf = sigmoidf_(gf);
            float so = sigmoidf_(go);
            float tg = tanhf_(gg);

            c = fmaf(sf, c, si * tg);
            h = so * tanhf_(c);

            const float4* wrow = reinterpret_cast<const float4*>(&sw[t*12]);
            float4 w0 = wrow[0];
            float4 w1 = wrow[1];
            float  w8 = sw[t*12 + 8];

            am0 = fmaf(h, w0.x, am0);
            am1 = fmaf(h, w0.y, am1);
            am2 = fmaf(h, w0.z, am2);
            av0 = fmaf(h, w0.w, av0);
            av1 = fmaf(h, w1.x, av1);
            av2 = fmaf(h, w1.y, av2);
            av3 = fmaf(h, w1.z, av3);
            av4 = fmaf(h, w1.w, av4);
            av5 = fmaf(h, w8,   av5);
        }
    }

    // ---- heads + gaussian NLL ----
    float m0 = am0 + bm[0], m1 = am1 + bm[1], m2 = am2 + bm[2];
    float e0 = av0 + bv[0], e1 = av1 + bv[1], e2 = av2 + bv[2];
    float e3 = av3 + bv[3], e4 = av4 + bv[4], e5 = av5 + bv[5];

    float tx = target[b*3+0], ty = target[b*3+1], tz = target[b*3+2];
    float rt0 = tx*b1x + ty*b1y + tz*b1z;
    float rt1 = tx*b2x + ty*b2y + tz*b2z;
    float rt2 = tx*c3x + ty*c3y + tz*c3z;

    float d0 = m0 - rt0, d1 = m1 - rt1, d2 = m2 - rt2;

    // quad = d^T (L D L^T)^{-1} d = z^T D^{-1} z, z = L^{-1} d
    float z0 = d0;
    float z1 = d1 - e0 * z0;
    float z2 = d2 - e1 * z0 - e2 * z1;

    float dv0 = __expf(e3), dv1 = __expf(e4), dv2 = __expf(e5);
    float quad = z0*z0*__expf(-e3) + z1*z1*__expf(-e4) + z2*z2*__expf(-e5);

    float val = 0.5f * (dv0 + dv1 + dv2 + quad);  // = -logprob_b

    // ---- block reduction ----
    sred[threadIdx.x] = val;
    __syncthreads();
    #pragma unroll
    for (int off = NTHREADS/2; off > 0; off >>= 1) {
        if (threadIdx.x < off) sred[threadIdx.x] += sred[threadIdx.x + off];
        __syncthreads();
    }
    if (threadIdx.x == 0) g_partial[blockIdx.x] = sred[0];
}

__global__ __launch_bounds__(NBLOCKS)
void reduce_kernel(float* __restrict__ out)
{
    __shared__ float s[NBLOCKS];
    int tid = threadIdx.x;
    s[tid] = g_partial[tid];
    __syncthreads();
    #pragma unroll
    for (int off = NBLOCKS/2; off > 0; off >>= 1) {
        if (tid < off) s[tid] += s[tid + off];
        __syncthreads();
    }
    if (tid == 0) out[0] = s[0] * (1.0f / 65536.0f);
}

extern "C" void kernel_launch(void* const* d_in, const int* in_sizes, int n_in,
                              void* d_out, int out_size)
{
    const float* hist   = (const float*)d_in[0];
    const float* h0     = (const float*)d_in[1];
    const float* c0     = (const float*)d_in[2];
    const float* target = (const float*)d_in[3];
    const float* Wih    = (const float*)d_in[4];
    const float* Whh    = (const float*)d_in[5];
    const float* bih    = (const float*)d_in[6];
    const float* bhh    = (const float*)d_in[7];
    const float* Wm     = (const float*)d_in[8];
    const float* bm     = (const float*)d_in[9];
    const float* Wv     = (const float*)d_in[10];
    const float* bv     = (const float*)d_in[11];

    recdyn_kernel<<<NBLOCKS, NTHREADS>>>(hist, h0, c0, target,
                                         Wih, Whh, bih, bhh, Wm, bm, Wv, bv);
    reduce_kernel<<<1, NBLOCKS>>>((float*)d_out);
}